// round 3
// baseline (speedup 1.0000x reference)
#include <cuda_runtime.h>
#include <math.h>
#include <stdint.h>

#define BB 64      // batch
#define EE 256     // embed
#define SS 32      // seq
#define HH 16      // heads
#define HD 16      // head dim
#define PP 512     // pairs
#define KC 46      // classes
#define MROWS (BB*SS)   // 2048
#define NCOLS (3*EE)    // 768

// ---------------- scratch (device globals; no allocation allowed) ----------
__device__ __align__(16) float g_QKV[MROWS * NCOLS];   // [m=b*32+s][n] n<256:Q, <512:K, <768:V
__device__ __align__(16) float g_G[BB * EE];           // sum_s fw[s] * O[b,s,:]
__device__ __align__(16) float g_logprob[BB * KC];     // log_softmax(logits) per b
__device__ int   g_sel[PP];
__device__ int   g_i[PP], g_j[PP];
__device__ float g_valid[PP];
__device__ float g_cj[BB];

// ---------------- 1) pair setup: mask scan, sel, i/j, valid, c_j, zero G ---
__global__ void pair_setup(const int* __restrict__ labels1) {
    __shared__ int l1[BB];
    __shared__ int cnt[256];
    __shared__ int off[257];
    __shared__ int cj[BB];
    int tid = threadIdx.x;
    for (int i = tid; i < BB * EE; i += 256) g_G[i] = 0.0f;   // zero accum target
    if (tid < BB) { l1[tid] = labels1[tid]; cj[tid] = 0; }
    __syncthreads();
    int base = tid * 16;
    int c = 0;
    #pragma unroll
    for (int u = 0; u < 16; u++) {
        int idx = base + u;
        c += (l1[idx >> 6] == l1[idx & 63]);
    }
    cnt[tid] = c;
    __syncthreads();
    if (tid == 0) {
        int acc = 0;
        for (int t = 0; t < 256; t++) { off[t] = acc; acc += cnt[t]; }
        off[256] = acc;
    }
    __syncthreads();
    int pos = off[tid];
    #pragma unroll
    for (int u = 0; u < 16; u++) {
        int idx = base + u;
        if (l1[idx >> 6] == l1[idx & 63]) {
            if (pos < PP) g_sel[pos] = idx;
            pos++;
        }
    }
    int total = off[256];
    for (int p2 = total + tid; p2 < PP; p2 += 256) g_sel[p2] = 0;  // fill_value=0
    __syncthreads();
    int nv = total < PP ? total : PP;
    for (int p = tid; p < PP; p += 256) {
        int s0 = g_sel[p];
        int i = s0 >> 6, j = s0 & 63;
        g_i[p] = i; g_j[p] = j;
        g_valid[p] = (p < nv) ? 1.0f : 0.0f;
        atomicAdd(&cj[j], 1);    // multiplicities over ALL P entries (fills included)
    }
    __syncthreads();
    if (tid < BB) g_cj[tid] = (float)cj[tid];
}

// ---------------- 2) QKV GEMM on tensor cores: split-TF32 ------------------
// C[2048][768] = A[2048][256] @ W[768][256]^T + bias
// A[m][k] = feat[b, k, s] (m = b*32+s).
// 3xTF32: x = hi + lo (both tf32-rounded); C ~= Ah*Bh + Ah*Bl + Al*Bh.
__device__ __forceinline__ void split_tf32(float x, float& hi, float& lo) {
    uint32_t u;
    asm("cvt.rna.tf32.f32 %0, %1;" : "=r"(u) : "f"(x));
    hi = __uint_as_float(u);
    float r = x - hi;
    asm("cvt.rna.tf32.f32 %0, %1;" : "=r"(u) : "f"(r));
    lo = __uint_as_float(u);
}

__device__ __forceinline__ void mma_tf32(float c[4], const float a[4], const float b[2]) {
    asm volatile(
        "mma.sync.aligned.m16n8k8.row.col.f32.tf32.tf32.f32 "
        "{%0,%1,%2,%3}, {%4,%5,%6,%7}, {%8,%9}, {%0,%1,%2,%3};"
        : "+f"(c[0]), "+f"(c[1]), "+f"(c[2]), "+f"(c[3])
        : "r"(__float_as_uint(a[0])), "r"(__float_as_uint(a[1])),
          "r"(__float_as_uint(a[2])), "r"(__float_as_uint(a[3])),
          "r"(__float_as_uint(b[0])), "r"(__float_as_uint(b[1])));
}

// block tile 128(M) x 64(N), 256 threads = 8 warps in 4x2, warp tile 32x32
__global__ void __launch_bounds__(256) qkv_gemm_tf32(const float* __restrict__ feat,
                                                     const float* __restrict__ W,
                                                     const float* __restrict__ bias) {
    __shared__ float Ah[128][36], Al[128][36];
    __shared__ float Bh[64][36],  Bl[64][36];
    int bm = blockIdx.x * 128, bn = blockIdx.y * 64;
    int tid = threadIdx.x;
    int warp = tid >> 5, lane = tid & 31;
    int wm = (warp >> 1) * 32;     // 0,32,64,96
    int wn = (warp & 1) * 32;      // 0,32
    int g = lane >> 2, tg = lane & 3;
    float c[2][4][4] = {};

    for (int k0 = 0; k0 < EE; k0 += 32) {
        // ---- A tile: 128 m x 32 k (m contiguous via s, float4) ----
        #pragma unroll
        for (int it = 0; it < 4; it++) {
            int idx = it * 256 + tid;          // 0..1023
            int k  = idx >> 5;                 // 0..31
            int m4 = (idx & 31) * 4;           // 0..124
            int m = bm + m4;
            int b = m >> 5, s = m & 31;
            float4 v = *(const float4*)(feat + b * (EE * SS) + (k0 + k) * SS + s);
            float h0, l0;
            split_tf32(v.x, h0, l0); Ah[m4][k]     = h0; Al[m4][k]     = l0;
            split_tf32(v.y, h0, l0); Ah[m4 + 1][k] = h0; Al[m4 + 1][k] = l0;
            split_tf32(v.z, h0, l0); Ah[m4 + 2][k] = h0; Al[m4 + 2][k] = l0;
            split_tf32(v.w, h0, l0); Ah[m4 + 3][k] = h0; Al[m4 + 3][k] = l0;
        }
        // ---- B tile: 64 n x 32 k (k contiguous, float4) ----
        #pragma unroll
        for (int it = 0; it < 2; it++) {
            int idx = it * 256 + tid;          // 0..511
            int n  = idx >> 3;                 // 0..63
            int k4 = (idx & 7) * 4;
            float4 v = *(const float4*)(W + (bn + n) * EE + k0 + k4);
            float h0, l0;
            split_tf32(v.x, h0, l0); Bh[n][k4]     = h0; Bl[n][k4]     = l0;
            split_tf32(v.y, h0, l0); Bh[n][k4 + 1] = h0; Bl[n][k4 + 1] = l0;
            split_tf32(v.z, h0, l0); Bh[n][k4 + 2] = h0; Bl[n][k4 + 2] = l0;
            split_tf32(v.w, h0, l0); Bh[n][k4 + 3] = h0; Bl[n][k4 + 3] = l0;
        }
        __syncthreads();
        #pragma unroll
        for (int kk = 0; kk < 32; kk += 8) {
            float ah[2][4], al[2][4];
            #pragma unroll
            for (int mi = 0; mi < 2; mi++) {
                int r0 = wm + mi * 16 + g;
                ah[mi][0] = Ah[r0][kk + tg];         ah[mi][1] = Ah[r0 + 8][kk + tg];
                ah[mi][2] = Ah[r0][kk + 4 + tg];     ah[mi][3] = Ah[r0 + 8][kk + 4 + tg];
                al[mi][0] = Al[r0][kk + tg];         al[mi][1] = Al[r0 + 8][kk + tg];
                al[mi][2] = Al[r0][kk + 4 + tg];     al[mi][3] = Al[r0 + 8][kk + 4 + tg];
            }
            float bh[4][2], bl[4][2];
            #pragma unroll
            for (int ni = 0; ni < 4; ni++) {
                int n0 = wn + ni * 8 + g;
                bh[ni][0] = Bh[n0][kk + tg];  bh[ni][1] = Bh[n0][kk + 4 + tg];
                bl[ni][0] = Bl[n0][kk + tg];  bl[ni][1] = Bl[n0][kk + 4 + tg];
            }
            #pragma unroll
            for (int mi = 0; mi < 2; mi++)
                #pragma unroll
                for (int ni = 0; ni < 4; ni++) {
                    mma_tf32(c[mi][ni], ah[mi], bh[ni]);
                    mma_tf32(c[mi][ni], ah[mi], bl[ni]);
                    mma_tf32(c[mi][ni], al[mi], bh[ni]);
                }
        }
        __syncthreads();
    }
    // ---- store with bias ----
    #pragma unroll
    for (int mi = 0; mi < 2; mi++) {
        int m = bm + wm + mi * 16 + g;
        #pragma unroll
        for (int ni = 0; ni < 4; ni++) {
            int n = bn + wn + ni * 8 + 2 * tg;
            float b0 = bias[n], b1 = bias[n + 1];
            float2 v0 = make_float2(c[mi][ni][0] + b0, c[mi][ni][1] + b1);
            float2 v1 = make_float2(c[mi][ni][2] + b0, c[mi][ni][3] + b1);
            *(float2*)(g_QKV + m * NCOLS + n) = v0;
            *(float2*)(g_QKV + (m + 8) * NCOLS + n) = v1;
        }
    }
}

// ---------------- 3) fused attention + seq-reduce --------------------------
// block = (h, s-chunk of 2); thread b computes count-weighted softmax row and
// accumulates fw[s] * o[b,s,h*16:..] into g_G via RED.F32.
__global__ void __launch_bounds__(64) attn_fused(const float* __restrict__ fw) {
    int h  = blockIdx.x & 15;
    int sc = blockIdx.x >> 4;    // 0..15
    __shared__ float Ks[BB][HD];
    __shared__ float Vs[BB][HD];
    __shared__ float Ss[BB][BB + 1];
    __shared__ float cjs[BB];
    int b = threadIdx.x;
    cjs[b] = g_cj[b];

    float gacc[HD];
    #pragma unroll
    for (int d = 0; d < HD; d++) gacc[d] = 0.0f;

    #pragma unroll
    for (int u = 0; u < 2; u++) {
        int s = sc * 2 + u;
        if (u) __syncthreads();   // previous iter's smem reads done
        const float* qkv_row = g_QKV + (b * SS + s) * NCOLS + h * HD;
        {
            const float4* kp = (const float4*)(qkv_row + EE);
            const float4* vp = (const float4*)(qkv_row + 2 * EE);
            float4* kd = (float4*)Ks[b];
            float4* vd = (float4*)Vs[b];
            kd[0] = kp[0]; kd[1] = kp[1]; kd[2] = kp[2]; kd[3] = kp[3];
            vd[0] = vp[0]; vd[1] = vp[1]; vd[2] = vp[2]; vd[3] = vp[3];
        }
        float4 q0 = ((const float4*)qkv_row)[0];
        float4 q1 = ((const float4*)qkv_row)[1];
        float4 q2 = ((const float4*)qkv_row)[2];
        float4 q3 = ((const float4*)qkv_row)[3];
        __syncthreads();

        float mx = -1e30f;
        #pragma unroll 4
        for (int j = 0; j < BB; j++) {
            const float4* kr = (const float4*)Ks[j];
            float4 k0 = kr[0], k1 = kr[1], k2 = kr[2], k3 = kr[3];
            float sv = q0.x * k0.x + q0.y * k0.y + q0.z * k0.z + q0.w * k0.w
                     + q1.x * k1.x + q1.y * k1.y + q1.z * k1.z + q1.w * k1.w
                     + q2.x * k2.x + q2.y * k2.y + q2.z * k2.z + q2.w * k2.w
                     + q3.x * k3.x + q3.y * k3.y + q3.z * k3.z + q3.w * k3.w;
            sv *= 0.25f;   // 1/sqrt(16)
            Ss[b][j] = sv;
            mx = fmaxf(mx, sv);
        }
        float denom = 0.0f;
        float acc[HD];
        #pragma unroll
        for (int d = 0; d < HD; d++) acc[d] = 0.0f;
        #pragma unroll 4
        for (int j = 0; j < BB; j++) {
            float p = cjs[j] * __expf(Ss[b][j] - mx);
            denom += p;
            const float4* vr = (const float4*)Vs[j];
            float4 v0 = vr[0], v1 = vr[1], v2 = vr[2], v3 = vr[3];
            acc[0] += p * v0.x;  acc[1] += p * v0.y;  acc[2] += p * v0.z;  acc[3] += p * v0.w;
            acc[4] += p * v1.x;  acc[5] += p * v1.y;  acc[6] += p * v1.z;  acc[7] += p * v1.w;
            acc[8] += p * v2.x;  acc[9] += p * v2.y;  acc[10] += p * v2.z; acc[11] += p * v2.w;
            acc[12] += p * v3.x; acc[13] += p * v3.y; acc[14] += p * v3.z; acc[15] += p * v3.w;
        }
        float wfs = fw[s] / denom;
        #pragma unroll
        for (int d = 0; d < HD; d++) gacc[d] += acc[d] * wfs;
    }
    float* gp = g_G + b * EE + h * HD;
    #pragma unroll
    for (int d = 0; d < HD; d++) atomicAdd(&gp[d], gacc[d]);
}

// ---------------- 4) head: h = G@Wo^T + sfw*bo + fb; logits; log_softmax ---
__global__ void __launch_bounds__(256) head_kernel(const float* __restrict__ Wo,
                                                   const float* __restrict__ bo,
                                                   const float* __restrict__ fw,
                                                   const float* __restrict__ fb,
                                                   const float* __restrict__ Hw,
                                                   const float* __restrict__ hb) {
    int b = blockIdx.x;
    __shared__ float Gs[EE];
    __shared__ float hs[EE];
    __shared__ float ls[64];
    __shared__ float sfw_sh;
    int tid = threadIdx.x;
    Gs[tid] = g_G[b * EE + tid];
    if (tid < 32) {
        float v = fw[tid];
        #pragma unroll
        for (int o = 16; o > 0; o >>= 1) v += __shfl_xor_sync(0xffffffffu, v, o);
        if (tid == 0) sfw_sh = v;
    }
    __syncthreads();
    int w = tid >> 5, lane = tid & 31;
    float fb0 = fb[0];
    for (int rr = 0; rr < 32; rr++) {
        int r = w * 32 + rr;
        const float* wrow = Wo + r * EE;
        float p = 0.0f;
        #pragma unroll
        for (int k = lane; k < EE; k += 32) p += Gs[k] * wrow[k];
        #pragma unroll
        for (int o = 16; o > 0; o >>= 1) p += __shfl_down_sync(0xffffffffu, p, o);
        if (lane == 0) hs[r] = p + sfw_sh * bo[r] + fb0;
    }
    __syncthreads();
    for (int r = w; r < KC; r += 8) {
        const float* hr = Hw + r * EE;
        float p = 0.0f;
        #pragma unroll
        for (int k = lane; k < EE; k += 32) p += hs[k] * hr[k];
        #pragma unroll
        for (int o = 16; o > 0; o >>= 1) p += __shfl_down_sync(0xffffffffu, p, o);
        if (lane == 0) ls[r] = p + hb[r];
    }
    __syncthreads();
    if (w == 0) {
        float v1 = (lane < KC) ? ls[lane] : -1e30f;
        float v2 = (lane + 32 < KC) ? ls[lane + 32] : -1e30f;
        float mx = fmaxf(v1, v2);
        #pragma unroll
        for (int o = 16; o > 0; o >>= 1) mx = fmaxf(mx, __shfl_xor_sync(0xffffffffu, mx, o));
        float se = ((lane < KC) ? __expf(v1 - mx) : 0.0f)
                 + ((lane + 32 < KC) ? __expf(v2 - mx) : 0.0f);
        #pragma unroll
        for (int o = 16; o > 0; o >>= 1) se += __shfl_xor_sync(0xffffffffu, se, o);
        float lse = mx + logf(se);
        if (lane < KC) g_logprob[b * KC + lane] = v1 - lse;
        if (lane + 32 < KC) g_logprob[b * KC + lane + 32] = v2 - lse;
    }
}

// ---------------- 5) loss: class counts, inverse-freq weights, weighted CE -
__global__ void __launch_bounds__(512) loss_kernel(const int* __restrict__ labels0,
                                                   float* __restrict__ out) {
    __shared__ int counts[KC];
    __shared__ float rn[16], rd[16];
    int tid = threadIdx.x;
    if (tid < KC) counts[tid] = 0;
    __syncthreads();
    int i = g_i[tid], j = g_j[tid];
    float valid = g_valid[tid];
    int a = labels0[i], c = labels0[j];
    int y;
    if (a == c) y = 0;
    else {
        int lo = min(a, c), hi = max(a, c);
        y = 1 + lo * 9 - (lo * (lo - 1)) / 2 + (hi - lo - 1);
    }
    if (valid > 0.0f) atomicAdd(&counts[y], 1);
    __syncthreads();
    float cw = counts[y] > 0 ? 1.0f / (float)counts[y] : 0.0f;
    float wy = cw * valid;
    float nll = -g_logprob[i * KC + y];
    float num = wy * nll, den = wy;
    int lane = tid & 31, w = tid >> 5;
    #pragma unroll
    for (int o = 16; o > 0; o >>= 1) {
        num += __shfl_down_sync(0xffffffffu, num, o);
        den += __shfl_down_sync(0xffffffffu, den, o);
    }
    if (lane == 0) { rn[w] = num; rd[w] = den; }
    __syncthreads();
    if (tid < 16) {
        num = rn[tid]; den = rd[tid];
        #pragma unroll
        for (int o = 8; o > 0; o >>= 1) {
            num += __shfl_down_sync(0xffffu, num, o);
            den += __shfl_down_sync(0xffffu, den, o);
        }
        if (tid == 0) out[0] = num / den;
    }
}

// ---------------------------------------------------------------------------
extern "C" void kernel_launch(void* const* d_in, const int* in_sizes, int n_in,
                              void* d_out, int out_size) {
    const float* feat    = (const float*)d_in[0];
    const int*   labels0 = (const int*)d_in[1];
    const int*   labels1 = (const int*)d_in[2];
    const float* ipw     = (const float*)d_in[3];
    const float* ipb     = (const float*)d_in[4];
    const float* opw     = (const float*)d_in[5];
    const float* opb     = (const float*)d_in[6];
    const float* fw      = (const float*)d_in[7];
    const float* fbv     = (const float*)d_in[8];
    const float* hw      = (const float*)d_in[9];
    const float* hbv     = (const float*)d_in[10];
    float* out = (float*)d_out;

    pair_setup<<<1, 256>>>(labels1);
    dim3 g(MROWS / 128, NCOLS / 64);         // 16 x 12
    qkv_gemm_tf32<<<g, 256>>>(feat, ipw, ipb);
    attn_fused<<<HH * 16, 64>>>(fw);         // 256 blocks
    head_kernel<<<BB, 256>>>(opw, opb, fw, fbv, hw, hbv);
    loss_kernel<<<1, 512>>>(labels0, out);
}

// round 5
// speedup vs baseline: 1.7320x; 1.7320x over previous
#include <cuda_runtime.h>
#include <math.h>

#define BB 64      // batch
#define EE 256     // embed
#define SS 32      // seq
#define HH 16      // heads
#define HD 16      // head dim
#define PP 512     // pairs
#define KC 46      // classes
#define MROWS (BB*SS)   // 2048
#define NCOLS (3*EE)    // 768

// ---------------- scratch (device globals; no allocation allowed) ----------
__device__ __align__(16) float g_QKV[MROWS * NCOLS];   // [m=b*32+s][n] n<256:Q, <512:K, <768:V
__device__ __align__(16) float g_O[BB * SS * EE];      // attention output per distinct i (=b)
__device__ __align__(16) float g_logprob[BB * KC];     // log_softmax(logits) per b
__device__ int   g_i[PP], g_j[PP];
__device__ float g_valid[PP];
__device__ float g_cj[BB];
__device__ int   g_sel[PP];

// ---------------- 1) pair setup: mask scan, sel, i/j, valid, c_j -----------
__global__ void pair_setup(const int* __restrict__ labels1) {
    __shared__ int l1[BB];
    __shared__ int cnt[256];
    __shared__ int off[257];
    __shared__ int cj[BB];
    int tid = threadIdx.x;
    if (tid < BB) { l1[tid] = labels1[tid]; cj[tid] = 0; }
    __syncthreads();
    int base = tid * 16;
    int c = 0;
    #pragma unroll
    for (int u = 0; u < 16; u++) {
        int idx = base + u;
        c += (l1[idx >> 6] == l1[idx & 63]);
    }
    cnt[tid] = c;
    __syncthreads();
    if (tid == 0) {
        int acc = 0;
        for (int t = 0; t < 256; t++) { off[t] = acc; acc += cnt[t]; }
        off[256] = acc;
    }
    __syncthreads();
    int pos = off[tid];
    #pragma unroll
    for (int u = 0; u < 16; u++) {
        int idx = base + u;
        if (l1[idx >> 6] == l1[idx & 63]) {
            if (pos < PP) g_sel[pos] = idx;
            pos++;
        }
    }
    int total = off[256];
    for (int p2 = total + tid; p2 < PP; p2 += 256) g_sel[p2] = 0;  // fill_value=0
    __syncthreads();
    int nv = total < PP ? total : PP;
    for (int p = tid; p < PP; p += 256) {
        int s0 = g_sel[p];
        int i = s0 >> 6, j = s0 & 63;
        g_i[p] = i; g_j[p] = j;
        g_valid[p] = (p < nv) ? 1.0f : 0.0f;
        atomicAdd(&cj[j], 1);    // multiplicities over ALL P entries (fills included)
    }
    __syncthreads();
    if (tid < BB) g_cj[tid] = (float)cj[tid];
}

// ---------------- 2) QKV projection GEMM: C[2048][768] = A @ W^T + b -------
// A[m][k] = feat[b, k, s]  (m = b*32+s), W = in_proj_w [768][256]
#define BM 64
#define BN 64
#define BK 16
__global__ void __launch_bounds__(256) qkv_gemm(const float* __restrict__ feat,
                                                const float* __restrict__ W,
                                                const float* __restrict__ bias) {
    __shared__ float As[BK][BM + 4];
    __shared__ float Bs[BK][BN + 4];
    int bm = blockIdx.x * BM, bn = blockIdx.y * BN;
    int tid = threadIdx.x;
    int tx = tid & 15, ty = tid >> 4;
    float acc[4][4] = {};
    for (int k0 = 0; k0 < EE; k0 += BK) {
        {   // A tile: 16k x 64m, 4 consecutive m per thread (contiguous s)
            int k  = tid >> 4;          // 0..15
            int m4 = (tid & 15) * 4;    // 0..60
            int m = bm + m4;
            int b = m >> 5, s = m & 31;
            float4 v = *(const float4*)(feat + b * (EE * SS) + (k0 + k) * SS + s);
            As[k][m4] = v.x; As[k][m4 + 1] = v.y; As[k][m4 + 2] = v.z; As[k][m4 + 3] = v.w;
        }
        {   // B tile: W[n][k], 4 consecutive k per thread, transpose into Bs[k][n]
            int n  = tid >> 2;          // 0..63
            int kk = (tid & 3) * 4;     // 0,4,8,12
            float4 v = *(const float4*)(W + (bn + n) * EE + k0 + kk);
            Bs[kk][n] = v.x; Bs[kk + 1][n] = v.y; Bs[kk + 2][n] = v.z; Bs[kk + 3][n] = v.w;
        }
        __syncthreads();
        #pragma unroll
        for (int k = 0; k < BK; k++) {
            float4 av = *(const float4*)&As[k][ty * 4];
            float4 bv = *(const float4*)&Bs[k][tx * 4];
            float a[4] = {av.x, av.y, av.z, av.w};
            float bb2[4] = {bv.x, bv.y, bv.z, bv.w};
            #pragma unroll
            for (int i = 0; i < 4; i++)
                #pragma unroll
                for (int j = 0; j < 4; j++)
                    acc[i][j] += a[i] * bb2[j];
        }
        __syncthreads();
    }
    #pragma unroll
    for (int i = 0; i < 4; i++) {
        int m = bm + ty * 4 + i;
        #pragma unroll
        for (int j = 0; j < 4; j++) {
            int n = bn + tx * 4 + j;
            g_QKV[m * NCOLS + n] = acc[i][j] + bias[n];
        }
    }
}

// ---------------- 3) attention per (s,h): count-weighted 64x64 softmax -----
__global__ void __launch_bounds__(64) attn_kernel() {
    int s = blockIdx.x & 31;
    int h = blockIdx.x >> 5;
    __shared__ float Ks[BB][HD];
    __shared__ float Vs[BB][HD];
    __shared__ float Ss[BB][BB + 1];
    __shared__ float cjs[BB];
    int b = threadIdx.x;   // 0..63, query row (distinct i)

    const float* qkv_row = g_QKV + (b * SS + s) * NCOLS + h * HD;
    {   // load K/V rows of this thread's b into smem
        const float4* kp = (const float4*)(qkv_row + EE);
        const float4* vp = (const float4*)(qkv_row + 2 * EE);
        float4* kd = (float4*)Ks[b];
        float4* vd = (float4*)Vs[b];
        kd[0] = kp[0]; kd[1] = kp[1]; kd[2] = kp[2]; kd[3] = kp[3];
        vd[0] = vp[0]; vd[1] = vp[1]; vd[2] = vp[2]; vd[3] = vp[3];
        cjs[b] = g_cj[b];
    }
    float4 q0 = ((const float4*)qkv_row)[0];
    float4 q1 = ((const float4*)qkv_row)[1];
    float4 q2 = ((const float4*)qkv_row)[2];
    float4 q3 = ((const float4*)qkv_row)[3];
    __syncthreads();

    float mx = -1e30f;
    #pragma unroll 4
    for (int j = 0; j < BB; j++) {
        const float4* kr = (const float4*)Ks[j];
        float4 k0 = kr[0], k1 = kr[1], k2 = kr[2], k3 = kr[3];
        float sc = q0.x * k0.x + q0.y * k0.y + q0.z * k0.z + q0.w * k0.w
                 + q1.x * k1.x + q1.y * k1.y + q1.z * k1.z + q1.w * k1.w
                 + q2.x * k2.x + q2.y * k2.y + q2.z * k2.z + q2.w * k2.w
                 + q3.x * k3.x + q3.y * k3.y + q3.z * k3.z + q3.w * k3.w;
        sc *= 0.25f;   // 1/sqrt(16)
        Ss[b][j] = sc;
        mx = fmaxf(mx, sc);
    }
    float denom = 0.0f;
    float acc[HD];
    #pragma unroll
    for (int d = 0; d < HD; d++) acc[d] = 0.0f;
    #pragma unroll 4
    for (int j = 0; j < BB; j++) {
        float p = cjs[j] * __expf(Ss[b][j] - mx);
        denom += p;
        const float4* vr = (const float4*)Vs[j];
        float4 v0 = vr[0], v1 = vr[1], v2 = vr[2], v3 = vr[3];
        acc[0] += p * v0.x;  acc[1] += p * v0.y;  acc[2] += p * v0.z;  acc[3] += p * v0.w;
        acc[4] += p * v1.x;  acc[5] += p * v1.y;  acc[6] += p * v1.z;  acc[7] += p * v1.w;
        acc[8] += p * v2.x;  acc[9] += p * v2.y;  acc[10] += p * v2.z; acc[11] += p * v2.w;
        acc[12] += p * v3.x; acc[13] += p * v3.y; acc[14] += p * v3.z; acc[15] += p * v3.w;
    }
    float inv = 1.0f / denom;
    float* op = g_O + (b * SS + s) * EE + h * HD;
    #pragma unroll
    for (int d = 0; d < HD; d++) op[d] = acc[d] * inv;
}

// ---------------- 4) head (fused seq-reduce): thread-per-output-column -----
// block b: G[e] = sum_s fw[s]*O[b,s,e]; h[r] = G.Wo[r] + sfw*bo[r] + fb;
// logits[r] = h.Hw[r] + hb[r]; log_softmax -> g_logprob[b].
__global__ void __launch_bounds__(256) head_kernel(const float* __restrict__ Wo,
                                                   const float* __restrict__ bo,
                                                   const float* __restrict__ fw,
                                                   const float* __restrict__ fb,
                                                   const float* __restrict__ Hw,
                                                   const float* __restrict__ hb) {
    int b = blockIdx.x;
    __shared__ float Gs[EE];
    __shared__ float hs[EE];
    __shared__ float ls[64];
    __shared__ float fws[SS];
    __shared__ float sfw_sh;
    int tid = threadIdx.x;
    if (tid < SS) fws[tid] = fw[tid];
    __syncthreads();
    if (tid < 32) {
        float v = fws[tid];
        #pragma unroll
        for (int o = 16; o > 0; o >>= 1) v += __shfl_xor_sync(0xffffffffu, v, o);
        if (tid == 0) sfw_sh = v;
    }
    // ---- G[e]: coalesced loads over s (independent, high MLP) ----
    {
        const float* ob = g_O + b * SS * EE + tid;
        float acc = 0.0f;
        #pragma unroll
        for (int s = 0; s < SS; s++) acc += ob[s * EE] * fws[s];
        Gs[tid] = acc;
    }
    __syncthreads();
    // ---- h[r] = dot(Gs, Wo[r]) : one row per thread, float4, full ILP ----
    {
        int r = tid;
        const float4* wrow = (const float4*)(Wo + r * EE);
        const float4* gv4 = (const float4*)Gs;
        float p = 0.0f;
        #pragma unroll 8
        for (int k = 0; k < EE / 4; k++) {
            float4 wv = wrow[k];
            float4 gv = gv4[k];   // smem broadcast across warp
            p += wv.x * gv.x + wv.y * gv.y + wv.z * gv.z + wv.w * gv.w;
        }
        hs[r] = p + sfw_sh * bo[r] + fb[0];
    }
    __syncthreads();
    // ---- logits: threads 0..45, one class row each ----
    if (tid < KC) {
        const float4* hrow = (const float4*)(Hw + tid * EE);
        const float4* hv4 = (const float4*)hs;
        float p = 0.0f;
        #pragma unroll 8
        for (int k = 0; k < EE / 4; k++) {
            float4 wv = hrow[k];
            float4 hv = hv4[k];
            p += wv.x * hv.x + wv.y * hv.y + wv.z * hv.z + wv.w * hv.w;
        }
        ls[tid] = p + hb[tid];
    }
    __syncthreads();
    // ---- log_softmax over 46 (warp 0) ----
    if (tid < 32) {
        int lane = tid;
        float v1 = (lane < KC) ? ls[lane] : -1e30f;
        float v2 = (lane + 32 < KC) ? ls[lane + 32] : -1e30f;
        float mx = fmaxf(v1, v2);
        #pragma unroll
        for (int o = 16; o > 0; o >>= 1) mx = fmaxf(mx, __shfl_xor_sync(0xffffffffu, mx, o));
        float se = ((lane < KC) ? __expf(v1 - mx) : 0.0f)
                 + ((lane + 32 < KC) ? __expf(v2 - mx) : 0.0f);
        #pragma unroll
        for (int o = 16; o > 0; o >>= 1) se += __shfl_xor_sync(0xffffffffu, se, o);
        float lse = mx + logf(se);
        if (lane < KC) g_logprob[b * KC + lane] = v1 - lse;
        if (lane + 32 < KC) g_logprob[b * KC + lane + 32] = v2 - lse;
    }
}

// ---------------- 5) loss: class counts, inverse-freq weights, weighted CE -
__global__ void __launch_bounds__(512) loss_kernel(const int* __restrict__ labels0,
                                                   float* __restrict__ out) {
    __shared__ int counts[KC];
    __shared__ float rn[16], rd[16];
    int tid = threadIdx.x;
    if (tid < KC) counts[tid] = 0;
    __syncthreads();
    int i = g_i[tid], j = g_j[tid];
    float valid = g_valid[tid];
    int a = labels0[i], c = labels0[j];
    int y;
    if (a == c) y = 0;
    else {
        int lo = min(a, c), hi = max(a, c);
        y = 1 + lo * 9 - (lo * (lo - 1)) / 2 + (hi - lo - 1);
    }
    if (valid > 0.0f) atomicAdd(&counts[y], 1);
    __syncthreads();
    float cw = counts[y] > 0 ? 1.0f / (float)counts[y] : 0.0f;
    float wy = cw * valid;
    float nll = -g_logprob[i * KC + y];
    float num = wy * nll, den = wy;
    int lane = tid & 31, w = tid >> 5;
    #pragma unroll
    for (int o = 16; o > 0; o >>= 1) {
        num += __shfl_down_sync(0xffffffffu, num, o);
        den += __shfl_down_sync(0xffffffffu, den, o);
    }
    if (lane == 0) { rn[w] = num; rd[w] = den; }
    __syncthreads();
    if (tid < 16) {
        num = rn[tid]; den = rd[tid];
        #pragma unroll
        for (int o = 8; o > 0; o >>= 1) {
            num += __shfl_down_sync(0xffffu, num, o);
            den += __shfl_down_sync(0xffffu, den, o);
        }
        if (tid == 0) out[0] = num / den;
    }
}

// ---------------------------------------------------------------------------
extern "C" void kernel_launch(void* const* d_in, const int* in_sizes, int n_in,
                              void* d_out, int out_size) {
    const float* feat    = (const float*)d_in[0];
    const int*   labels0 = (const int*)d_in[1];
    const int*   labels1 = (const int*)d_in[2];
    const float* ipw     = (const float*)d_in[3];
    const float* ipb     = (const float*)d_in[4];
    const float* opw     = (const float*)d_in[5];
    const float* opb     = (const float*)d_in[6];
    const float* fw      = (const float*)d_in[7];
    const float* fbv     = (const float*)d_in[8];
    const float* hw      = (const float*)d_in[9];
    const float* hbv     = (const float*)d_in[10];
    float* out = (float*)d_out;

    pair_setup<<<1, 256>>>(labels1);
    dim3 g(MROWS / BM, NCOLS / BN);          // 32 x 12
    qkv_gemm<<<g, 256>>>(feat, ipw, ipb);
    attn_kernel<<<SS * HH, 64>>>();          // 512 blocks
    head_kernel<<<BB, 256>>>(opw, opb, fw, fbv, hw, hbv);
    loss_kernel<<<1, 512>>>(labels0, out);
}

// round 6
// speedup vs baseline: 1.8985x; 1.0962x over previous
#include <cuda_runtime.h>
#include <math.h>
#include <stdint.h>

#define BB 64      // batch
#define EE 256     // embed
#define SS 32      // seq
#define HH 16      // heads
#define HD 16      // head dim
#define PP 512     // pairs
#define KC 46      // classes
#define MROWS (BB*SS)   // 2048
#define NCOLS (3*EE)    // 768
#define NMT (MROWS/16)  // 128 m-tiles
#define NNT (NCOLS/8)   // 96 n-tiles
#define NKS (EE/8)      // 32 k-steps

// ---------------- scratch (device globals; no allocation allowed) ----------
__device__ __align__(16) float g_Afrag[NMT * NKS * 32 * 8];  // canned A frags (hi4,lo4)
__device__ __align__(16) float g_Bfrag[NNT * NKS * 32 * 4];  // canned B frags (bh0,bh1,bl0,bl1)
__device__ __align__(16) float g_QKV[MROWS * NCOLS];
__device__ __align__(16) float g_O[BB * SS * EE];
__device__ __align__(16) float g_logprob[BB * KC];
__device__ int   g_i[PP], g_j[PP];
__device__ float g_valid[PP];
__device__ float g_cj[BB];
__device__ int   g_sel[PP];

__device__ __forceinline__ void split_tf32(float x, float& hi, float& lo) {
    uint32_t u;
    asm("cvt.rna.tf32.f32 %0, %1;" : "=r"(u) : "f"(x));
    hi = __uint_as_float(u);
    float r = x - hi;
    asm("cvt.rna.tf32.f32 %0, %1;" : "=r"(u) : "f"(r));
    lo = __uint_as_float(u);
}

__device__ __forceinline__ void mma_tf32(float c[4], float a0, float a1, float a2, float a3,
                                         float b0, float b1) {
    asm volatile(
        "mma.sync.aligned.m16n8k8.row.col.f32.tf32.tf32.f32 "
        "{%0,%1,%2,%3}, {%4,%5,%6,%7}, {%8,%9}, {%0,%1,%2,%3};"
        : "+f"(c[0]), "+f"(c[1]), "+f"(c[2]), "+f"(c[3])
        : "r"(__float_as_uint(a0)), "r"(__float_as_uint(a1)),
          "r"(__float_as_uint(a2)), "r"(__float_as_uint(a3)),
          "r"(__float_as_uint(b0)), "r"(__float_as_uint(b1)));
}

// ---------------- 1) fused setup: A-split | B-split | pair scan ------------
// blocks 0..63: split A (per batch b); 64..159: split B (per n-tile); 160: pairs
__global__ void __launch_bounds__(256) setup_kernel(const float* __restrict__ feat,
                                                    const float* __restrict__ W,
                                                    const int* __restrict__ labels1) {
    int tid = threadIdx.x;
    int bx = blockIdx.x;
    if (bx < 64) {
        // ---- A split: A[m][k] = feat[b, k, s], m = b*32+s ----
        __shared__ float sA[256][33];    // [k][s]
        int b = bx;
        int s = tid & 31, k0 = tid >> 5;
        for (int k = k0; k < 256; k += 8)
            sA[k][s] = feat[b * 8192 + k * 32 + s];
        __syncthreads();
        #pragma unroll
        for (int t = 0; t < 8; t++) {
            int idx = t * 256 + tid;          // 0..2047
            int mt_l = idx >> 10;             // 0..1
            int rem = idx & 1023;
            int ks = rem >> 5, lane = rem & 31;
            int g = lane >> 2, tg = lane & 3;
            int r0 = mt_l * 16 + g;
            int k1 = ks * 8 + tg, k2 = k1 + 4;
            float a0 = sA[k1][r0], a1 = sA[k1][r0 + 8];
            float a2 = sA[k2][r0], a3 = sA[k2][r0 + 8];
            float h0, l0, h1, l1, h2, l2, h3, l3;
            split_tf32(a0, h0, l0); split_tf32(a1, h1, l1);
            split_tf32(a2, h2, l2); split_tf32(a3, h3, l3);
            int mt = b * 2 + mt_l;
            float4* dst = (float4*)&g_Afrag[((mt * NKS + ks) * 32 + lane) * 8];
            dst[0] = make_float4(h0, h1, h2, h3);
            dst[1] = make_float4(l0, l1, l2, l3);
        }
    } else if (bx < 160) {
        // ---- B split: B[n][k] = W[n][k] ----
        __shared__ float sW[8][260];
        int nt = bx - 64;
        int row = tid >> 5;            // 0..7
        int kk = (tid & 31) * 8;
        const float* wr = W + (nt * 8 + row) * 256 + kk;
        #pragma unroll
        for (int u = 0; u < 8; u++) sW[row][kk + u] = wr[u];
        __syncthreads();
        #pragma unroll
        for (int t = 0; t < 4; t++) {
            int idx = t * 256 + tid;       // 0..1023
            int ks = idx >> 5, lane = idx & 31;
            int g = lane >> 2, tg = lane & 3;
            float b0 = sW[g][ks * 8 + tg], b1 = sW[g][ks * 8 + 4 + tg];
            float h0, l0, h1, l1;
            split_tf32(b0, h0, l0);
            split_tf32(b1, h1, l1);
            ((float4*)g_Bfrag)[(nt * NKS + ks) * 32 + lane] = make_float4(h0, h1, l0, l1);
        }
    } else {
        // ---- pair setup ----
        __shared__ int l1[BB];
        __shared__ int cnt[256];
        __shared__ int off[257];
        __shared__ int cj[BB];
        if (tid < BB) { l1[tid] = labels1[tid]; cj[tid] = 0; }
        __syncthreads();
        int base = tid * 16;
        int c = 0;
        #pragma unroll
        for (int u = 0; u < 16; u++) {
            int idx = base + u;
            c += (l1[idx >> 6] == l1[idx & 63]);
        }
        cnt[tid] = c;
        __syncthreads();
        if (tid == 0) {
            int acc = 0;
            for (int t = 0; t < 256; t++) { off[t] = acc; acc += cnt[t]; }
            off[256] = acc;
        }
        __syncthreads();
        int pos = off[tid];
        #pragma unroll
        for (int u = 0; u < 16; u++) {
            int idx = base + u;
            if (l1[idx >> 6] == l1[idx & 63]) {
                if (pos < PP) g_sel[pos] = idx;
                pos++;
            }
        }
        int total = off[256];
        for (int p2 = total + tid; p2 < PP; p2 += 256) g_sel[p2] = 0;
        __syncthreads();
        int nv = total < PP ? total : PP;
        for (int p = tid; p < PP; p += 256) {
            int s0 = g_sel[p];
            int i = s0 >> 6, j = s0 & 63;
            g_i[p] = i; g_j[p] = j;
            g_valid[p] = (p < nv) ? 1.0f : 0.0f;
            atomicAdd(&cj[j], 1);
        }
        __syncthreads();
        if (tid < BB) g_cj[tid] = (float)cj[tid];
    }
}

// ---------------- 2) QKV GEMM: smem-free fragment-direct tf32x3 ------------
// block tile 128(M) x 64(N); warp tile 32x32; no smem, no syncs.
__global__ void __launch_bounds__(256, 2) qkv_mma(const float* __restrict__ bias) {
    int bx = blockIdx.x;   // 0..15 (M)
    int by = blockIdx.y;   // 0..11 (N)
    int tid = threadIdx.x, warp = tid >> 5, lane = tid & 31;
    int g = lane >> 2, tg = lane & 3;
    int mtb = bx * 8 + (warp >> 1) * 2;   // first of 2 m-tiles
    int ntb = by * 8 + (warp & 1) * 4;    // first of 4 n-tiles
    float c[2][4][4] = {};
    const float4* Af = (const float4*)g_Afrag;
    const float4* Bf = (const float4*)g_Bfrag;
    #pragma unroll 4
    for (int ks = 0; ks < NKS; ks++) {
        float4 ah[2], al[2], bf[4];
        #pragma unroll
        for (int mi = 0; mi < 2; mi++) {
            int ia = (((mtb + mi) * NKS + ks) * 32 + lane) * 2;
            ah[mi] = Af[ia];
            al[mi] = Af[ia + 1];
        }
        #pragma unroll
        for (int ni = 0; ni < 4; ni++)
            bf[ni] = Bf[((ntb + ni) * NKS + ks) * 32 + lane];
        #pragma unroll
        for (int mi = 0; mi < 2; mi++)
            #pragma unroll
            for (int ni = 0; ni < 4; ni++) {
                mma_tf32(c[mi][ni], ah[mi].x, ah[mi].y, ah[mi].z, ah[mi].w, bf[ni].x, bf[ni].y);
                mma_tf32(c[mi][ni], ah[mi].x, ah[mi].y, ah[mi].z, ah[mi].w, bf[ni].z, bf[ni].w);
                mma_tf32(c[mi][ni], al[mi].x, al[mi].y, al[mi].z, al[mi].w, bf[ni].x, bf[ni].y);
            }
    }
    #pragma unroll
    for (int mi = 0; mi < 2; mi++) {
        int m = bx * 128 + (warp >> 1) * 32 + mi * 16 + g;
        #pragma unroll
        for (int ni = 0; ni < 4; ni++) {
            int n = by * 64 + (warp & 1) * 32 + ni * 8 + 2 * tg;
            float b0 = bias[n], b1 = bias[n + 1];
            *(float2*)(g_QKV + m * NCOLS + n) = make_float2(c[mi][ni][0] + b0, c[mi][ni][1] + b1);
            *(float2*)(g_QKV + (m + 8) * NCOLS + n) = make_float2(c[mi][ni][2] + b0, c[mi][ni][3] + b1);
        }
    }
}

// ---------------- 3) attention per (s,h): count-weighted 64x64 softmax -----
__global__ void __launch_bounds__(64) attn_kernel() {
    int s = blockIdx.x & 31;
    int h = blockIdx.x >> 5;
    __shared__ float Ks[BB][HD];
    __shared__ float Vs[BB][HD];
    __shared__ float Ss[BB][BB + 1];
    __shared__ float cjs[BB];
    int b = threadIdx.x;

    const float* qkv_row = g_QKV + (b * SS + s) * NCOLS + h * HD;
    {
        const float4* kp = (const float4*)(qkv_row + EE);
        const float4* vp = (const float4*)(qkv_row + 2 * EE);
        float4* kd = (float4*)Ks[b];
        float4* vd = (float4*)Vs[b];
        kd[0] = kp[0]; kd[1] = kp[1]; kd[2] = kp[2]; kd[3] = kp[3];
        vd[0] = vp[0]; vd[1] = vp[1]; vd[2] = vp[2]; vd[3] = vp[3];
        cjs[b] = g_cj[b];
    }
    float4 q0 = ((const float4*)qkv_row)[0];
    float4 q1 = ((const float4*)qkv_row)[1];
    float4 q2 = ((const float4*)qkv_row)[2];
    float4 q3 = ((const float4*)qkv_row)[3];
    __syncthreads();

    float mx = -1e30f;
    #pragma unroll 4
    for (int j = 0; j < BB; j++) {
        const float4* kr = (const float4*)Ks[j];
        float4 k0 = kr[0], k1 = kr[1], k2 = kr[2], k3 = kr[3];
        float sc = q0.x * k0.x + q0.y * k0.y + q0.z * k0.z + q0.w * k0.w
                 + q1.x * k1.x + q1.y * k1.y + q1.z * k1.z + q1.w * k1.w
                 + q2.x * k2.x + q2.y * k2.y + q2.z * k2.z + q2.w * k2.w
                 + q3.x * k3.x + q3.y * k3.y + q3.z * k3.z + q3.w * k3.w;
        sc *= 0.25f;
        Ss[b][j] = sc;
        mx = fmaxf(mx, sc);
    }
    float denom = 0.0f;
    float acc[HD];
    #pragma unroll
    for (int d = 0; d < HD; d++) acc[d] = 0.0f;
    #pragma unroll 4
    for (int j = 0; j < BB; j++) {
        float p = cjs[j] * __expf(Ss[b][j] - mx);
        denom += p;
        const float4* vr = (const float4*)Vs[j];
        float4 v0 = vr[0], v1 = vr[1], v2 = vr[2], v3 = vr[3];
        acc[0] += p * v0.x;  acc[1] += p * v0.y;  acc[2] += p * v0.z;  acc[3] += p * v0.w;
        acc[4] += p * v1.x;  acc[5] += p * v1.y;  acc[6] += p * v1.z;  acc[7] += p * v1.w;
        acc[8] += p * v2.x;  acc[9] += p * v2.y;  acc[10] += p * v2.z; acc[11] += p * v2.w;
        acc[12] += p * v3.x; acc[13] += p * v3.y; acc[14] += p * v3.z; acc[15] += p * v3.w;
    }
    float inv = 1.0f / denom;
    float* op = g_O + (b * SS + s) * EE + h * HD;
    #pragma unroll
    for (int d = 0; d < HD; d++) op[d] = acc[d] * inv;
}

// ---------------- 4) head (fused seq-reduce) -------------------------------
__global__ void __launch_bounds__(256) head_kernel(const float* __restrict__ Wo,
                                                   const float* __restrict__ bo,
                                                   const float* __restrict__ fw,
                                                   const float* __restrict__ fb,
                                                   const float* __restrict__ Hw,
                                                   const float* __restrict__ hb) {
    int b = blockIdx.x;
    __shared__ float Gs[EE];
    __shared__ float hs[EE];
    __shared__ float ls[64];
    __shared__ float fws[SS];
    __shared__ float sfw_sh;
    int tid = threadIdx.x;
    if (tid < SS) fws[tid] = fw[tid];
    __syncthreads();
    if (tid < 32) {
        float v = fws[tid];
        #pragma unroll
        for (int o = 16; o > 0; o >>= 1) v += __shfl_xor_sync(0xffffffffu, v, o);
        if (tid == 0) sfw_sh = v;
    }
    {
        const float* ob = g_O + b * SS * EE + tid;
        float acc = 0.0f;
        #pragma unroll
        for (int s = 0; s < SS; s++) acc += ob[s * EE] * fws[s];
        Gs[tid] = acc;
    }
    __syncthreads();
    {
        int r = tid;
        const float4* wrow = (const float4*)(Wo + r * EE);
        const float4* gv4 = (const float4*)Gs;
        float p = 0.0f;
        #pragma unroll 8
        for (int k = 0; k < EE / 4; k++) {
            float4 wv = wrow[k];
            float4 gv = gv4[k];
            p += wv.x * gv.x + wv.y * gv.y + wv.z * gv.z + wv.w * gv.w;
        }
        hs[r] = p + sfw_sh * bo[r] + fb[0];
    }
    __syncthreads();
    if (tid < KC) {
        const float4* hrow = (const float4*)(Hw + tid * EE);
        const float4* hv4 = (const float4*)hs;
        float p = 0.0f;
        #pragma unroll 8
        for (int k = 0; k < EE / 4; k++) {
            float4 wv = hrow[k];
            float4 hv = hv4[k];
            p += wv.x * hv.x + wv.y * hv.y + wv.z * hv.z + wv.w * hv.w;
        }
        ls[tid] = p + hb[tid];
    }
    __syncthreads();
    if (tid < 32) {
        int lane = tid;
        float v1 = (lane < KC) ? ls[lane] : -1e30f;
        float v2 = (lane + 32 < KC) ? ls[lane + 32] : -1e30f;
        float mx = fmaxf(v1, v2);
        #pragma unroll
        for (int o = 16; o > 0; o >>= 1) mx = fmaxf(mx, __shfl_xor_sync(0xffffffffu, mx, o));
        float se = ((lane < KC) ? __expf(v1 - mx) : 0.0f)
                 + ((lane + 32 < KC) ? __expf(v2 - mx) : 0.0f);
        #pragma unroll
        for (int o = 16; o > 0; o >>= 1) se += __shfl_xor_sync(0xffffffffu, se, o);
        float lse = mx + logf(se);
        if (lane < KC) g_logprob[b * KC + lane] = v1 - lse;
        if (lane + 32 < KC) g_logprob[b * KC + lane + 32] = v2 - lse;
    }
}

// ---------------- 5) loss --------------------------------------------------
__global__ void __launch_bounds__(512) loss_kernel(const int* __restrict__ labels0,
                                                   float* __restrict__ out) {
    __shared__ int counts[KC];
    __shared__ float rn[16], rd[16];
    int tid = threadIdx.x;
    if (tid < KC) counts[tid] = 0;
    __syncthreads();
    int i = g_i[tid], j = g_j[tid];
    float valid = g_valid[tid];
    int a = labels0[i], c = labels0[j];
    int y;
    if (a == c) y = 0;
    else {
        int lo = min(a, c), hi = max(a, c);
        y = 1 + lo * 9 - (lo * (lo - 1)) / 2 + (hi - lo - 1);
    }
    if (valid > 0.0f) atomicAdd(&counts[y], 1);
    __syncthreads();
    float cw = counts[y] > 0 ? 1.0f / (float)counts[y] : 0.0f;
    float wy = cw * valid;
    float nll = -g_logprob[i * KC + y];
    float num = wy * nll, den = wy;
    int lane = tid & 31, w = tid >> 5;
    #pragma unroll
    for (int o = 16; o > 0; o >>= 1) {
        num += __shfl_down_sync(0xffffffffu, num, o);
        den += __shfl_down_sync(0xffffffffu, den, o);
    }
    if (lane == 0) { rn[w] = num; rd[w] = den; }
    __syncthreads();
    if (tid < 16) {
        num = rn[tid]; den = rd[tid];
        #pragma unroll
        for (int o = 8; o > 0; o >>= 1) {
            num += __shfl_down_sync(0xffffu, num, o);
            den += __shfl_down_sync(0xffffu, den, o);
        }
        if (tid == 0) out[0] = num / den;
    }
}

// ---------------------------------------------------------------------------
extern "C" void kernel_launch(void* const* d_in, const int* in_sizes, int n_in,
                              void* d_out, int out_size) {
    const float* feat    = (const float*)d_in[0];
    const int*   labels0 = (const int*)d_in[1];
    const int*   labels1 = (const int*)d_in[2];
    const float* ipw     = (const float*)d_in[3];
    const float* ipb     = (const float*)d_in[4];
    const float* opw     = (const float*)d_in[5];
    const float* opb     = (const float*)d_in[6];
    const float* fw      = (const float*)d_in[7];
    const float* fbv     = (const float*)d_in[8];
    const float* hw      = (const float*)d_in[9];
    const float* hbv     = (const float*)d_in[10];
    float* out = (float*)d_out;

    setup_kernel<<<161, 256>>>(feat, ipw, labels1);
    dim3 g(MROWS / 128, NCOLS / 64);          // 16 x 12
    qkv_mma<<<g, 256>>>(ipb);
    attn_kernel<<<SS * HH, 64>>>();           // 512 blocks
    head_kernel<<<BB, 256>>>(opw, opb, fw, fbv, hw, hbv);
    loss_kernel<<<1, 512>>>(labels0, out);
}